// round 11
// baseline (speedup 1.0000x reference)
#include <cuda_runtime.h>
#include <cstdint>

// Problem constants
#define NN_ 2048
#define BB_ 16
#define DD_ 8
#define TRACE_ROWS 16                     // gridDim.x(=2) * 16 = 32 trace blocks

static __device__ __constant__ const float kAlpha = 0.95122945f;
static __device__ __constant__ const float kOneMinusAlpha = 1.0f - 0.95122945f;

// Shared layout (floats):
//   s_w    [16][1024]  W ring               = 16384
//   s_dmB  [8][1024]   tile-B dmap stage    =  8192
//   s_apB  [1024], s_adB [1024]             =  2048
//   s_pre  [2][128], s_xd [2][128]          =   512
#define SW_FLOATS    (BB_ * 1024)
#define SDM_FLOATS   (DD_ * 1024)
#define SMEM_FLOATS  (SW_FLOATS + SDM_FLOATS + 1024 + 1024 + 512)

#define CP_ASYNC16(smem_u32, gptr) \
    asm volatile("cp.async.cg.shared.global [%0], [%1], 16;" \
                 :: "r"(smem_u32), "l"(gptr) : "memory")
#define CP_COMMIT() asm volatile("cp.async.commit_group;" ::: "memory")
#define CP_WAIT(n)  asm volatile("cp.async.wait_group %0;" :: "n"(n) : "memory")

__device__ __forceinline__ uint32_t smem_u32(const void* p) {
    return (uint32_t)__cvta_generic_to_shared(p);
}

// ---------------------------------------------------------------------------
// Two e-rows per block, single 16-slot ring, LAZY tile-B issue:
//   prologue : A-groups 0..7 (W of e0), then dmap/A_p/A_d of e1 -> smem   (9 groups)
//   A-steps  : wait(8) -> process A group g -> issue B group g into the
//              just-consumed slots -> commit   (pipeline stays 8 deep)
//   boundary : wait(8) -> dm/ap/ad for e1 from per-thread smem slots
//   B-steps  : wait(7..0) -> process B groups (issued early, rarely stall)
// Slot reuse is WAR-safe: each thread reads only its own 16B slot and the
// LDS result is consumed before the cp.async issues in program order.
// ---------------------------------------------------------------------------
__global__ void __launch_bounds__(256, 2) stdp_fused(
    const float* __restrict__ Xd,        // [D,B,N]
    const float* __restrict__ Xpost,     // [B,N]
    const float* __restrict__ xbar_pre,  // [D,B,N]
    const float* __restrict__ xbar_post, // [B,N]
    const float* __restrict__ W,         // [B,N,N] (b,e,o)
    const float* __restrict__ A_p,       // [N,N]   (e,o)
    const float* __restrict__ A_d,       // [N,N]   (e,o)
    const float* __restrict__ dmap,      // [D,N,N] (d,e,o)
    float* __restrict__ out,             // [B,N,N]
    float* __restrict__ Wnew,            // [B,N,N]
    float* __restrict__ pre_out,         // [D,B,N]
    float* __restrict__ post_out)        // [B,N]
{
    extern __shared__ float sm[];
    float* s_w   = sm;                          // [16][1024]
    float* s_dmB = sm + SW_FLOATS;              // [8][1024]
    float* s_apB = s_dmB + SDM_FLOATS;          // [1024]
    float* s_adB = s_apB + 1024;                // [1024]
    float* s_pre = s_adB + 1024;                // [2][128]
    float* s_xd  = s_pre + 2 * 128;             // [2][128]

    if (blockIdx.y < TRACE_ROWS) {
        // ---- trace-update stream (scheduled early, overlaps main waves) ----
        const int vb = blockIdx.y * gridDim.x + blockIdx.x;   // 0..31
        const int tg = vb * 256 + threadIdx.x;
        const int npre = DD_ * BB_ * NN_ / 4;   // 65536
        const int ntot = npre + BB_ * NN_ / 4;  // 73728
        for (int i = tg; i < ntot; i += TRACE_ROWS * 2 * 256) {
            float4 x, xb;
            if (i < npre) {
                x  = reinterpret_cast<const float4*>(Xd)[i];
                xb = reinterpret_cast<const float4*>(xbar_pre)[i];
            } else {
                x  = reinterpret_cast<const float4*>(Xpost)[i - npre];
                xb = reinterpret_cast<const float4*>(xbar_post)[i - npre];
            }
            float4 r;
            r.x = fmaf(kAlpha, xb.x, kOneMinusAlpha * x.x);
            r.y = fmaf(kAlpha, xb.y, kOneMinusAlpha * x.y);
            r.z = fmaf(kAlpha, xb.z, kOneMinusAlpha * x.z);
            r.w = fmaf(kAlpha, xb.w, kOneMinusAlpha * x.w);
            if (i < npre) reinterpret_cast<float4*>(pre_out)[i] = r;
            else          reinterpret_cast<float4*>(post_out)[i - npre] = r;
        }
        return;
    }

    // ---- main STDP path: two e-rows per block ----
    const int e0 = (blockIdx.y - TRACE_ROWS) * 2;      // e1 = e0 + 1
    const int t  = threadIdx.x;
    const int o  = blockIdx.x * 1024 + t * 4;
    const size_t eoA = (size_t)e0 * NN_ + o;
    const size_t eoB = eoA + NN_;

    // Tile-A b-invariant planes: register-resident (consumed first).
    float4 dm[DD_];
#pragma unroll
    for (int d = 0; d < DD_; d++)
        dm[d] = __ldcs(reinterpret_cast<const float4*>(dmap + (size_t)d * NN_ * NN_ + eoA));
    float4 ap = __ldcs(reinterpret_cast<const float4*>(A_p + eoA));
    float4 ad = __ldcs(reinterpret_cast<const float4*>(A_d + eoA));

    const uint32_t swa  = smem_u32(s_w)   + (uint32_t)t * 16u;
    const uint32_t sdma = smem_u32(s_dmB) + (uint32_t)t * 16u;
    const uint32_t sapa = smem_u32(s_apB) + (uint32_t)t * 16u;
    const uint32_t sada = smem_u32(s_adB) + (uint32_t)t * 16u;

    // Prologue: A-groups 0..7, then the dmB stage group (9 commits).
#pragma unroll
    for (int g = 0; g < 8; g++) {
        CP_ASYNC16(swa + (uint32_t)(2 * g)     * 4096u, W + (size_t)(2 * g)     * NN_ * NN_ + eoA);
        CP_ASYNC16(swa + (uint32_t)(2 * g + 1) * 4096u, W + (size_t)(2 * g + 1) * NN_ * NN_ + eoA);
        CP_COMMIT();
    }
#pragma unroll
    for (int d = 0; d < DD_; d++)
        CP_ASYNC16(sdma + (uint32_t)d * 4096u, dmap + (size_t)d * NN_ * NN_ + eoB);
    CP_ASYNC16(sapa, A_p + eoB);
    CP_ASYNC16(sada, A_d + eoB);
    CP_COMMIT();

    // Per-(e) scalars for BOTH tiles, before the single barrier.
    if (t < 128) {
        const int d = t >> 4, b = t & 15;
        s_pre[t]       = xbar_pre[((size_t)d * BB_ + b) * NN_ + e0];
        s_pre[128 + t] = xbar_pre[((size_t)d * BB_ + b) * NN_ + e0 + 1];
    } else {
        const int i = t - 128;
        const int d = i >> 4, b = i & 15;
        s_xd[i]       = Xd[((size_t)d * BB_ + b) * NN_ + e0];
        s_xd[128 + i] = Xd[((size_t)d * BB_ + b) * NN_ + e0 + 1];
    }
    __syncthreads();

#define PROCESS2(B0, EO, PAR)                                                   \
    {                                                                           \
        _Pragma("unroll")                                                       \
        for (int j = 0; j < 2; j++) {                                           \
            const int b = (B0) + j;                                             \
            float4 pot = make_float4(0.f, 0.f, 0.f, 0.f);                       \
            float4 dep = make_float4(0.f, 0.f, 0.f, 0.f);                       \
            _Pragma("unroll")                                                   \
            for (int d = 0; d < DD_; d++) {                                     \
                const float p = s_pre[(PAR) * 128 + d * BB_ + b];               \
                pot.x = fmaf(dm[d].x, p, pot.x);                                \
                pot.y = fmaf(dm[d].y, p, pot.y);                                \
                pot.z = fmaf(dm[d].z, p, pot.z);                                \
                pot.w = fmaf(dm[d].w, p, pot.w);                                \
                const float q = s_xd[(PAR) * 128 + d * BB_ + b];                \
                dep.x = fmaf(dm[d].x, q, dep.x);                                \
                dep.y = fmaf(dm[d].y, q, dep.y);                                \
                dep.z = fmaf(dm[d].z, q, dep.z);                                \
                dep.w = fmaf(dm[d].w, q, dep.w);                                \
            }                                                                   \
            const float4 xp = *reinterpret_cast<const float4*>(                 \
                Xpost + (size_t)b * NN_ + o);                                   \
            const float4 xb = *reinterpret_cast<const float4*>(                 \
                xbar_post + (size_t)b * NN_ + o);                               \
            const float4 w = *reinterpret_cast<const float4*>(                  \
                s_w + b * 1024 + t * 4);                                        \
            const size_t idx = (size_t)b * NN_ * NN_ + (EO);                    \
            *reinterpret_cast<float4*>(out + idx) = w;                          \
            float4 wn;                                                          \
            wn.x = fminf(fmaxf(fmaf(xp.x * ap.x, pot.x,                         \
                        fmaf(-xb.x * ad.x, dep.x, w.x)), 0.f), 1.f);            \
            wn.y = fminf(fmaxf(fmaf(xp.y * ap.y, pot.y,                         \
                        fmaf(-xb.y * ad.y, dep.y, w.y)), 0.f), 1.f);            \
            wn.z = fminf(fmaxf(fmaf(xp.z * ap.z, pot.z,                         \
                        fmaf(-xb.z * ad.z, dep.z, w.z)), 0.f), 1.f);            \
            wn.w = fminf(fmaxf(fmaf(xp.w * ap.w, pot.w,                         \
                        fmaf(-xb.w * ad.w, dep.w, w.w)), 0.f), 1.f);            \
            *reinterpret_cast<float4*>(Wnew + idx) = wn;                        \
        }                                                                       \
    }

// Issue tile-B group g into the slots just consumed by tile-A group g.
#define ISSUE_B(G)                                                              \
    {                                                                           \
        CP_ASYNC16(swa + (uint32_t)(2 * (G))     * 4096u,                       \
                   W + (size_t)(2 * (G))     * NN_ * NN_ + eoB);                \
        CP_ASYNC16(swa + (uint32_t)(2 * (G) + 1) * 4096u,                       \
                   W + (size_t)(2 * (G) + 1) * NN_ * NN_ + eoB);                \
        CP_COMMIT();                                                            \
    }

    // ---- Tile A: constant 8-deep pipeline (9 pending before each wait) ----
    CP_WAIT(8); PROCESS2(0,  eoA, 0); ISSUE_B(0);
    CP_WAIT(8); PROCESS2(2,  eoA, 0); ISSUE_B(1);
    CP_WAIT(8); PROCESS2(4,  eoA, 0); ISSUE_B(2);
    CP_WAIT(8); PROCESS2(6,  eoA, 0); ISSUE_B(3);
    CP_WAIT(8); PROCESS2(8,  eoA, 0); ISSUE_B(4);
    CP_WAIT(8); PROCESS2(10, eoA, 0); ISSUE_B(5);
    CP_WAIT(8); PROCESS2(12, eoA, 0); ISSUE_B(6);
    CP_WAIT(8); PROCESS2(14, eoA, 0); ISSUE_B(7);

    // ---- Boundary: dmB stage landed; read per-thread smem slots ----
    CP_WAIT(8);
#pragma unroll
    for (int d = 0; d < DD_; d++)
        dm[d] = *reinterpret_cast<const float4*>(s_dmB + d * 1024 + t * 4);
    ap = *reinterpret_cast<const float4*>(s_apB + t * 4);
    ad = *reinterpret_cast<const float4*>(s_adB + t * 4);

    // ---- Tile B (groups were issued early; drain 7..0) ----
    CP_WAIT(7); PROCESS2(0,  eoB, 1);
    CP_WAIT(6); PROCESS2(2,  eoB, 1);
    CP_WAIT(5); PROCESS2(4,  eoB, 1);
    CP_WAIT(4); PROCESS2(6,  eoB, 1);
    CP_WAIT(3); PROCESS2(8,  eoB, 1);
    CP_WAIT(2); PROCESS2(10, eoB, 1);
    CP_WAIT(1); PROCESS2(12, eoB, 1);
    CP_WAIT(0); PROCESS2(14, eoB, 1);
#undef PROCESS2
#undef ISSUE_B
}

extern "C" void kernel_launch(void* const* d_in, const int* in_sizes, int n_in,
                              void* d_out, int out_size)
{
    const float* Xd        = (const float*)d_in[0]; // (D,B,N)
    const float* Xpost     = (const float*)d_in[1]; // (B,N)
    const float* xbar_pre  = (const float*)d_in[2]; // (D,B,N)
    const float* xbar_post = (const float*)d_in[3]; // (B,N)
    const float* W         = (const float*)d_in[4]; // (B,N,N)
    const float* A_p       = (const float*)d_in[5]; // (N,N)
    const float* A_d       = (const float*)d_in[6]; // (N,N)
    const float* dmap      = (const float*)d_in[7]; // (D,N,N)

    float* out      = (float*)d_out;
    float* Wnew     = out  + (size_t)BB_ * NN_ * NN_;
    float* pre_out  = Wnew + (size_t)BB_ * NN_ * NN_;
    float* post_out = pre_out + (size_t)DD_ * BB_ * NN_;

    const int smem_bytes = SMEM_FLOATS * sizeof(float);   // ~108.5KB
    static int attr_set = 0;
    if (!attr_set) {
        cudaFuncSetAttribute(stdp_fused,
                             cudaFuncAttributeMaxDynamicSharedMemorySize,
                             smem_bytes);
        attr_set = 1;
    }

    // grid.y: 16 trace rows + 1024 e-pair rows
    dim3 grid(NN_ / (256 * 4), TRACE_ROWS + NN_ / 2);   // (2, 1040)
    stdp_fused<<<grid, 256, smem_bytes>>>(
        Xd, Xpost, xbar_pre, xbar_post, W, A_p, A_d, dmap,
        out, Wnew, pre_out, post_out);
}

// round 12
// speedup vs baseline: 1.5475x; 1.5475x over previous
#include <cuda_runtime.h>
#include <cstdint>

// Problem constants
#define NN_ 2048
#define BB_ 16
#define DD_ 8
#define TRACE_ROWS 16                     // gridDim.x(=2) * 16 = 32 trace blocks

static __device__ __constant__ const float kAlpha = 0.95122945f;
static __device__ __constant__ const float kOneMinusAlpha = 1.0f - 0.95122945f;

// Shared layout (dynamic): W stage [16][1024] floats, then s_pre[8][16], s_xd[8][16]
#define SW_FLOATS   (BB_ * 1024)          // 16384 floats = 64KB
#define SMEM_FLOATS (SW_FLOATS + 2 * DD_ * BB_)

#define CP_ASYNC16(smem_u32, gptr) \
    asm volatile("cp.async.cg.shared.global [%0], [%1], 16;" \
                 :: "r"(smem_u32), "l"(gptr) : "memory")
#define CP_COMMIT() asm volatile("cp.async.commit_group;" ::: "memory")
#define CP_WAIT(n)  asm volatile("cp.async.wait_group %0;" :: "n"(n) : "memory")

__device__ __forceinline__ uint32_t smem_u32(const void* p) {
    return (uint32_t)__cvta_generic_to_shared(p);
}

// ---------------------------------------------------------------------------
// Fused kernel (R7 structure: dm register-resident, 2 CTAs/SM).
//   blockIdx.y <  TRACE_ROWS : trace-update elementwise stream (~3MB).
//   blockIdx.y >= TRACE_ROWS : main STDP update, e = blockIdx.y - TRACE_ROWS.
//     W staged via cp.async: 8 commit-groups of 2 b-tiles; consumption starts
//     as soon as group 0 lands (wait_group 7).
// ---------------------------------------------------------------------------
__global__ void __launch_bounds__(256, 2) stdp_fused(
    const float* __restrict__ Xd,        // [D,B,N]
    const float* __restrict__ Xpost,     // [B,N]
    const float* __restrict__ xbar_pre,  // [D,B,N]
    const float* __restrict__ xbar_post, // [B,N]
    const float* __restrict__ W,         // [B,N,N] (b,e,o)
    const float* __restrict__ A_p,       // [N,N]   (e,o)
    const float* __restrict__ A_d,       // [N,N]   (e,o)
    const float* __restrict__ dmap,      // [D,N,N] (d,e,o)
    float* __restrict__ out,             // [B,N,N]
    float* __restrict__ Wnew,            // [B,N,N]
    float* __restrict__ pre_out,         // [D,B,N]
    float* __restrict__ post_out)        // [B,N]
{
    extern __shared__ float sm[];
    float* s_w   = sm;                    // [16][1024]
    float* s_pre = sm + SW_FLOATS;        // [8][16]
    float* s_xd  = s_pre + DD_ * BB_;     // [8][16]

    if (blockIdx.y < TRACE_ROWS) {
        // ---- trace-update stream (scheduled early, overlaps main waves) ----
        const int vb = blockIdx.y * gridDim.x + blockIdx.x;   // 0..31
        const int tg = vb * 256 + threadIdx.x;
        const int npre = DD_ * BB_ * NN_ / 4;   // 65536
        const int ntot = npre + BB_ * NN_ / 4;  // 73728
        for (int i = tg; i < ntot; i += TRACE_ROWS * 2 * 256) {
            float4 x, xb;
            if (i < npre) {
                x  = reinterpret_cast<const float4*>(Xd)[i];
                xb = reinterpret_cast<const float4*>(xbar_pre)[i];
            } else {
                x  = reinterpret_cast<const float4*>(Xpost)[i - npre];
                xb = reinterpret_cast<const float4*>(xbar_post)[i - npre];
            }
            float4 r;
            r.x = fmaf(kAlpha, xb.x, kOneMinusAlpha * x.x);
            r.y = fmaf(kAlpha, xb.y, kOneMinusAlpha * x.y);
            r.z = fmaf(kAlpha, xb.z, kOneMinusAlpha * x.z);
            r.w = fmaf(kAlpha, xb.w, kOneMinusAlpha * x.w);
            if (i < npre) __stcs(reinterpret_cast<float4*>(pre_out) + i, r);
            else          __stcs(reinterpret_cast<float4*>(post_out) + (i - npre), r);
        }
        return;
    }

    // ---- main STDP path ----
    const int e = blockIdx.y - TRACE_ROWS;
    const int t = threadIdx.x;
    const int o = blockIdx.x * 1024 + t * 4;
    const size_t eo = (size_t)e * NN_ + o;

    // b-invariant planes FIRST (consumed earliest): register-resident for the
    // whole b-loop. This pins regs near 128 -> exactly 2 CTAs/SM; L1 cannot be
    // relied on here (smem carveout), so registers are the right home.
    float4 dm[DD_];
#pragma unroll
    for (int d = 0; d < DD_; d++)
        dm[d] = __ldcs(reinterpret_cast<const float4*>(dmap + (size_t)d * NN_ * NN_ + eo));
    const float4 ap = __ldcs(reinterpret_cast<const float4*>(A_p + eo));
    const float4 ad = __ldcs(reinterpret_cast<const float4*>(A_d + eo));

    // Async-stage all 16 W[b] tiles: 8 commit-groups of 2.
    const uint32_t swa = smem_u32(s_w + t * 4);
#pragma unroll
    for (int g = 0; g < 8; g++) {
#pragma unroll
        for (int j = 0; j < 2; j++) {
            const int b = g * 2 + j;
            CP_ASYNC16(swa + (uint32_t)b * 4096u, W + (size_t)b * NN_ * NN_ + eo);
        }
        CP_COMMIT();
    }

    // Per-(e) scalars.
    if (t < DD_ * BB_) {
        const int d = t >> 4, b = t & 15;
        s_pre[t] = xbar_pre[((size_t)d * BB_ + b) * NN_ + e];
    } else {
        const int i = t - DD_ * BB_;
        const int d = i >> 4, b = i & 15;
        s_xd[i] = Xd[((size_t)d * BB_ + b) * NN_ + e];
    }
    __syncthreads();

#define PROCESS2(B0)                                                            \
    {                                                                           \
        _Pragma("unroll")                                                       \
        for (int j = 0; j < 2; j++) {                                           \
            const int b = (B0) + j;                                             \
            float4 pot = make_float4(0.f, 0.f, 0.f, 0.f);                       \
            float4 dep = make_float4(0.f, 0.f, 0.f, 0.f);                       \
            _Pragma("unroll")                                                   \
            for (int d = 0; d < DD_; d++) {                                     \
                const float p = s_pre[d * BB_ + b];                             \
                pot.x = fmaf(dm[d].x, p, pot.x);                                \
                pot.y = fmaf(dm[d].y, p, pot.y);                                \
                pot.z = fmaf(dm[d].z, p, pot.z);                                \
                pot.w = fmaf(dm[d].w, p, pot.w);                                \
                const float q = s_xd[d * BB_ + b];                              \
                dep.x = fmaf(dm[d].x, q, dep.x);                                \
                dep.y = fmaf(dm[d].y, q, dep.y);                                \
                dep.z = fmaf(dm[d].z, q, dep.z);                                \
                dep.w = fmaf(dm[d].w, q, dep.w);                                \
            }                                                                   \
            const float4 xp = *reinterpret_cast<const float4*>(                 \
                Xpost + (size_t)b * NN_ + o);                                   \
            const float4 xb = *reinterpret_cast<const float4*>(                 \
                xbar_post + (size_t)b * NN_ + o);                               \
            const float4 w = *reinterpret_cast<const float4*>(                  \
                s_w + b * 1024 + t * 4);                                        \
            const size_t idx = (size_t)b * NN_ * NN_ + eo;                      \
            __stcs(reinterpret_cast<float4*>(out + idx), w);                    \
            float4 wn;                                                          \
            wn.x = fminf(fmaxf(fmaf(xp.x * ap.x, pot.x,                         \
                        fmaf(-xb.x * ad.x, dep.x, w.x)), 0.f), 1.f);            \
            wn.y = fminf(fmaxf(fmaf(xp.y * ap.y, pot.y,                         \
                        fmaf(-xb.y * ad.y, dep.y, w.y)), 0.f), 1.f);            \
            wn.z = fminf(fmaxf(fmaf(xp.z * ap.z, pot.z,                         \
                        fmaf(-xb.z * ad.z, dep.z, w.z)), 0.f), 1.f);            \
            wn.w = fminf(fmaxf(fmaf(xp.w * ap.w, pot.w,                         \
                        fmaf(-xb.w * ad.w, dep.w, w.w)), 0.f), 1.f);            \
            __stcs(reinterpret_cast<float4*>(Wnew + idx), wn);                  \
        }                                                                       \
    }

    CP_WAIT(7); PROCESS2(0);   // start as soon as group 0's 8KB lands
    CP_WAIT(6); PROCESS2(2);
    CP_WAIT(5); PROCESS2(4);
    CP_WAIT(4); PROCESS2(6);
    CP_WAIT(3); PROCESS2(8);
    CP_WAIT(2); PROCESS2(10);
    CP_WAIT(1); PROCESS2(12);
    CP_WAIT(0); PROCESS2(14);
#undef PROCESS2
}

extern "C" void kernel_launch(void* const* d_in, const int* in_sizes, int n_in,
                              void* d_out, int out_size)
{
    const float* Xd        = (const float*)d_in[0]; // (D,B,N)
    const float* Xpost     = (const float*)d_in[1]; // (B,N)
    const float* xbar_pre  = (const float*)d_in[2]; // (D,B,N)
    const float* xbar_post = (const float*)d_in[3]; // (B,N)
    const float* W         = (const float*)d_in[4]; // (B,N,N)
    const float* A_p       = (const float*)d_in[5]; // (N,N)
    const float* A_d       = (const float*)d_in[6]; // (N,N)
    const float* dmap      = (const float*)d_in[7]; // (D,N,N)

    float* out      = (float*)d_out;
    float* Wnew     = out  + (size_t)BB_ * NN_ * NN_;
    float* pre_out  = Wnew + (size_t)BB_ * NN_ * NN_;
    float* post_out = pre_out + (size_t)DD_ * BB_ * NN_;

    const int smem_bytes = SMEM_FLOATS * sizeof(float);   // ~66KB
    static int attr_set = 0;
    if (!attr_set) {
        cudaFuncSetAttribute(stdp_fused,
                             cudaFuncAttributeMaxDynamicSharedMemorySize,
                             smem_bytes);
        attr_set = 1;
    }

    dim3 grid(NN_ / (256 * 4), NN_ + TRACE_ROWS);   // (2, 2064)
    stdp_fused<<<grid, 256, smem_bytes>>>(
        Xd, Xpost, xbar_pre, xbar_post, W, A_p, A_d, dmap,
        out, Wnew, pre_out, post_out);
}